// round 14
// baseline (speedup 1.0000x reference)
#include <cuda_runtime.h>
#include <cstdint>

// ---------------- problem constants ----------------
#define B_SZ    64
#define D_SZ    920          // 23*40
#define K_SEL   32
#define NROWS   (B_SZ * D_SZ)      // 58880 sample-rows (b, n)
#define WARPS_PER_CTA 8
#define THREADS (WARPS_PER_CTA * 32)
#define CAP     128
#define NBINS   128
#define T0F     0.90f        // prefilter threshold (exact-count fallback below)

// scratch (all __device__ globals; no allocations)
__device__ unsigned short      g_sel[NROWS * K_SEL];       // 3.68 MB selected indices
__device__ unsigned long long  g_act[B_SZ * D_SZ];         // per-b active list (tf<<32|d)
__device__ int                 g_actcnt[B_SZ];             // per-b active counts
__device__ float               g_red[B_SZ * 8 * K_SEL];    // stage-1 partials

// ---------------- threefry2x32, key=(0,1), partitionable fold ----------------
// Plain adds: ptxas balances IMAD/IADD3 across pipes itself; forcing IMAD
// measured +22us (cross-pipe RAW = 5 on the serial round chain).
__device__ __forceinline__ unsigned tf_bits(unsigned ctr) {
    unsigned x0 = 0u, x1 = ctr;
    const unsigned k0 = 0u, k1 = 1u, kx = 0x1BD11BDBu;
    x0 += k0; x1 += k1;
#define TFR(r) { x0 += x1; x1 = __funnelshift_l(x1, x1, (r)); x1 ^= x0; }
    TFR(13) TFR(15) TFR(26) TFR(6)
    x0 += k1; x1 += kx + 1u;
    TFR(17) TFR(29) TFR(16) TFR(24)
    x0 += kx; x1 += k0 + 2u;
    TFR(13) TFR(15) TFR(26) TFR(6)
    x0 += k0; x1 += k1 + 3u;
    TFR(17) TFR(29) TFR(16) TFR(24)
    x0 += k1; x1 += kx + 4u;
#undef TFR
    return x0 ^ x1;
}

// ---------------- XLA ErfInv32 (identical numerics to passing rounds) --------
__device__ __forceinline__ float erfinv_xla(float x) {
    float w = -log1pf(-__fmul_rn(x, x));
    float p;
    if (w < 5.0f) {
        w = w - 2.5f;
        p = 2.81022636e-08f;
        p = fmaf(p, w, 3.43273939e-07f);
        p = fmaf(p, w, -3.5233877e-06f);
        p = fmaf(p, w, -4.39150654e-06f);
        p = fmaf(p, w, 0.00021858087f);
        p = fmaf(p, w, -0.00125372503f);
        p = fmaf(p, w, -0.00417768164f);
        p = fmaf(p, w, 0.246640727f);
        p = fmaf(p, w, 1.50140941f);
    } else {
        w = sqrtf(w) - 3.0f;
        p = -0.000200214257f;
        p = fmaf(p, w, 0.000100950558f);
        p = fmaf(p, w, 0.00134934322f);
        p = fmaf(p, w, -0.00367342844f);
        p = fmaf(p, w, 0.00573950773f);
        p = fmaf(p, w, -0.0076224613f);
        p = fmaf(p, w, 0.00943887047f);
        p = fmaf(p, w, 1.00167406f);
        p = fmaf(p, w, 2.83297682f);
    }
    return __fmul_rn(p, x);
}

// exact perturbed value from the 23 uniform bits (must match all rounds' path)
__device__ __forceinline__ float pert_from_v23(unsigned v23, float wad) {
    float f = __uint_as_float(v23 | 0x3F800000u) - 1.0f;   // [0,1)
    float u = __fadd_rn(__fmul_rn(f, 2.0f), -0.99999994f);
    float nrm = __fmul_rn(1.41421356f, erfinv_xla(u));
    return __fadd_rn(wad, __fmul_rn(nrm, 0.1f));
}

__device__ __forceinline__ unsigned orderable(float v) {
    unsigned u = __float_as_uint(v);
    return (u & 0x80000000u) ? ~u : (u | 0x80000000u);
}
// monotone quantizer into 128 bins over the competitive range (~0.9..1.32)
__device__ __forceinline__ int qbin_of(float pert) {
    int q = (int)fmaf(pert, 300.0f, -260.0f);
    return min(NBINS - 1, max(0, q));
}

// =============================================================================
// Kernel A: zero the per-b active counters (device globals persist across
// graph replays, so this must run every launch).
// =============================================================================
__global__ void init_kernel() {
    if (threadIdx.x < B_SZ) g_actcnt[threadIdx.x] = 0;
}

// =============================================================================
// Kernel 0: full-chip grid-stride. Per-(b,d) exact 23-step bisection for the
// minimal v23 with pert > T0; d with NO qualifying v23 are dropped. Survivors
// appended to g_act[b] via global atomic (order nondeterministic — selection-
// neutral, validated bit-identical in R12). 64-ULP conservative slack.
// =============================================================================
__global__ void __launch_bounds__(256)
thresh_kernel(const float* __restrict__ wa) {
    int i = blockIdx.x * 256 + threadIdx.x;
    if (i >= B_SZ * D_SZ) return;
    const int b = i / D_SZ;
    const int d = i - b * D_SZ;
    float wad = wa[i];
    unsigned lo = 0u, hi = 0x800000u;     // hi sentinel: no v qualifies
    #pragma unroll 1
    for (int it = 0; it < 24; ++it) {
        if (lo >= hi) break;
        unsigned mid = (lo + hi) >> 1;
        if (pert_from_v23(mid, wad) > T0F) hi = mid; else lo = mid + 1u;
    }
    if (lo < 0x800000u) {                 // qualification possible
        unsigned t  = (lo >= 64u) ? (lo - 64u) : 0u;   // 64-ULP slack (superset)
        unsigned tf = t << 9;             // compare against full 32-bit bits
        int pos = atomicAdd(&g_actcnt[b], 1);
        g_act[(size_t)b * D_SZ + pos] =
            ((unsigned long long)tf << 32) | (unsigned)d;
    }
}

// exact-pert generation pass (fallback only; full d scan, independent of g_act)
template<bool STORE>
__device__ __forceinline__ int gen_exact(const float* s_wa, unsigned gbase, float T,
                                         unsigned long long* cand, int lane) {
    const unsigned ltmask = (1u << lane) - 1u;
    int base = 0;
    for (int i = 0; i < 29; ++i) {
        int d = (i << 5) + lane;
        bool valid = (d < D_SZ);
        unsigned bits = valid ? tf_bits(gbase + (unsigned)d) : 0u;
        float pert = valid ? pert_from_v23(bits >> 9, s_wa[d]) : -1e30f;
        bool pred = valid && (pert > T);
        unsigned bal = __ballot_sync(0xFFFFFFFFu, pred);
        if (STORE && pred) {
            int slot = base + __popc(bal & ltmask);
            if (slot < CAP)
                cand[slot] = ((unsigned long long)bits << 32) | (unsigned)d;
        }
        base += __popc(bal);
    }
    return base;
}

// =============================================================================
// Kernel 1: warp-per-row; hot loop over the COMPACTED active list only
// (threefry + 32-bit compare). 4 independent chains per lane; candidate
// insertion via per-warp smem atomic (selection math is order-independent).
// =============================================================================
__global__ void __launch_bounds__(THREADS)
row_topk_kernel(const float* __restrict__ wa) {
    __shared__ float              s_wa[D_SZ];
    __shared__ unsigned long long s_act[D_SZ];
    __shared__ unsigned long long s_cand[WARPS_PER_CTA][CAP];
    __shared__ unsigned           s_hist[WARPS_PER_CTA][NBINS];
    __shared__ unsigned char      s_qb[WARPS_PER_CTA][CAP];
    __shared__ unsigned           s_sel[WARPS_PER_CTA][K_SEL];
    __shared__ unsigned           s_chosen[WARPS_PER_CTA][CAP / 32];
    __shared__ int                s_cnt[WARPS_PER_CTA];

    const int tid  = threadIdx.x;
    const int w    = tid >> 5;
    const int lane = tid & 31;
    const int row  = blockIdx.x * WARPS_PER_CTA + w;
    const int b    = (blockIdx.x * WARPS_PER_CTA) / D_SZ;   // same b across CTA

    const int nact = g_actcnt[b];
    for (int d = tid; d < D_SZ; d += THREADS)
        s_wa[d] = wa[(size_t)b * D_SZ + d];
    for (int j = tid; j < nact; j += THREADS)
        s_act[j] = g_act[(size_t)b * D_SZ + j];
    if (lane == 0) s_cnt[w] = 0;
    __syncthreads();            // the only block barrier

    unsigned long long* cand = s_cand[w];
    const unsigned gbase  = (unsigned)row * (unsigned)D_SZ;
    const unsigned ltmask = (1u << lane) - 1u;

    // ---- integer-only generate over active list: 4 chains, no ballots ----
    const int nfull = nact & ~127;
    #pragma unroll 1
    for (int j0 = 0; j0 < nfull; j0 += 128) {
        int j = j0 + lane;
        unsigned long long e0 = s_act[j];
        unsigned long long e1 = s_act[j + 32];
        unsigned long long e2 = s_act[j + 64];
        unsigned long long e3 = s_act[j + 96];
        unsigned d0 = (unsigned)e0, d1 = (unsigned)e1,
                 d2 = (unsigned)e2, d3 = (unsigned)e3;
        unsigned bb0 = tf_bits(gbase + d0);
        unsigned bb1 = tf_bits(gbase + d1);
        unsigned bb2 = tf_bits(gbase + d2);
        unsigned bb3 = tf_bits(gbase + d3);
        if (bb0 >= (unsigned)(e0 >> 32)) {
            int s = atomicAdd(&s_cnt[w], 1);
            if (s < CAP) cand[s] = ((unsigned long long)bb0 << 32) | d0;
        }
        if (bb1 >= (unsigned)(e1 >> 32)) {
            int s = atomicAdd(&s_cnt[w], 1);
            if (s < CAP) cand[s] = ((unsigned long long)bb1 << 32) | d1;
        }
        if (bb2 >= (unsigned)(e2 >> 32)) {
            int s = atomicAdd(&s_cnt[w], 1);
            if (s < CAP) cand[s] = ((unsigned long long)bb2 << 32) | d2;
        }
        if (bb3 >= (unsigned)(e3 >> 32)) {
            int s = atomicAdd(&s_cnt[w], 1);
            if (s < CAP) cand[s] = ((unsigned long long)bb3 << 32) | d3;
        }
    }
    #pragma unroll 1
    for (int j0 = nfull; j0 < nact; j0 += 32) {     // remainder, 1 chain
        int j = j0 + lane;
        if (j < nact) {
            unsigned long long e = s_act[j];
            unsigned d = (unsigned)e;
            unsigned bb = tf_bits(gbase + d);
            if (bb >= (unsigned)(e >> 32)) {
                int s = atomicAdd(&s_cnt[w], 1);
                if (s < CAP) cand[s] = ((unsigned long long)bb << 32) | d;
            }
        }
    }
    __syncwarp();
    int m = s_cnt[w];

    // ---- exact pert/key conversion for candidates; exact above-T0 count ------
    auto convert = [&](int mm) -> int {
        int cnt = 0;
        for (int c = lane; c < mm; c += 32) {
            unsigned long long e = cand[c];
            unsigned bits = (unsigned)(e >> 32);
            unsigned d    = (unsigned)(e & 0xFFFFFFFFull);
            float pert = pert_from_v23(bits >> 9, s_wa[d]);
            cnt += (pert > T0F);
            cand[c] = ((unsigned long long)orderable(pert) << 32) | (unsigned)(~d);
            s_qb[w][c] = (unsigned char)qbin_of(pert);
        }
        __syncwarp();
        return __reduce_add_sync(0xFFFFFFFFu, cnt);
    };

    int mm = min(m, CAP);
    int mex = convert(mm);

    if (m > CAP || mex < K_SEL) {
        // exact fallback (never fires for this distribution): bisect a value
        // threshold with K_SEL <= count <= CAP using exact pert over ALL d
        float lo = -0.7f, hi = 1.6f, T = T0F;
        #pragma unroll 1
        for (int it = 0; it < 24; ++it) {
            T = 0.5f * (lo + hi);
            int c = gen_exact<false>(s_wa, gbase, T, cand, lane);
            if (c < K_SEL)      hi = T;
            else if (c > CAP)   lo = T;
            else break;
        }
        m  = gen_exact<true>(s_wa, gbase, T, cand, lane);
        mm = min(m, CAP);
        convert(mm);
    }

    // ---- fine histogram over mm candidates (128 bins) ----
    #pragma unroll
    for (int j = lane; j < NBINS; j += 32) s_hist[w][j] = 0u;
    __syncwarp();
    for (int c = lane; c < mm; c += 32)
        atomicAdd(&s_hist[w][s_qb[w][c]], 1u);
    __syncwarp();

    // ---- suffix scan: boundary bin Bq, count strictly above ----
    unsigned h[4], t = 0;
    #pragma unroll
    for (int j = 0; j < 4; ++j) { h[j] = s_hist[w][(lane << 2) + j]; t += h[j]; }
    unsigned x = t;
    #pragma unroll
    for (int off = 1; off < 32; off <<= 1) {
        unsigned y = __shfl_down_sync(0xFFFFFFFFu, x, off);
        if (lane + off < 32) x += y;
    }
    unsigned run = x - t;
    int Bq_l = -1; unsigned above_l = 0;
    #pragma unroll
    for (int j = 3; j >= 0; --j) {
        unsigned inc = run + h[j];
        if (run < K_SEL && inc >= K_SEL) { Bq_l = (lane << 2) + j; above_l = run; }
        run = inc;
    }
    unsigned fb = __ballot_sync(0xFFFFFFFFu, Bq_l >= 0);
    int src = __ffs(fb) - 1;
    const int      Bq    = __shfl_sync(0xFFFFFFFFu, Bq_l, src);
    const unsigned above = __shfl_sync(0xFFFFFFFFu, above_l, src);
    const unsigned need  = K_SEL - above;

    // ---- exact boundary tie-break: top `need` of bin Bq by (key desc, d asc) --
    #pragma unroll
    for (int j = lane; j < CAP / 32; j += 32) s_chosen[w][j] = 0u;
    __syncwarp();
    for (unsigned it = 0; it < need; ++it) {
        unsigned long long best = 0ull; int bpos = -1;
        for (int c = lane; c < mm; c += 32) {
            if (s_qb[w][c] == (unsigned char)Bq &&
                !((s_chosen[w][c >> 5] >> (c & 31)) & 1u)) {
                unsigned long long v = cand[c];
                if (v > best) { best = v; bpos = c; }
            }
        }
        #pragma unroll
        for (int off = 16; off; off >>= 1) {
            unsigned long long ob = __shfl_down_sync(0xFFFFFFFFu, best, off);
            int op = __shfl_down_sync(0xFFFFFFFFu, bpos, off);
            if (ob > best) { best = ob; bpos = op; }
        }
        bpos = __shfl_sync(0xFFFFFFFFu, bpos, 0);
        if (lane == 0 && bpos >= 0)                       // defensive: no wild write
            s_chosen[w][bpos >> 5] |= 1u << (bpos & 31);
        __syncwarp();
    }

    // ---- gather 32 selected indices (unordered) ----
    int sbase = 0;
    for (int c0 = 0; c0 < mm; c0 += 32) {
        int c = c0 + lane;
        bool pred = false; unsigned d = 0;
        if (c < mm) {
            bool win = ((int)s_qb[w][c] > Bq) ||
                       (((s_chosen[w][c >> 5] >> (c & 31)) & 1u) != 0u);
            if (win) { pred = true; d = ~(unsigned)(cand[c] & 0xFFFFFFFFull); }
        }
        unsigned bal = __ballot_sync(0xFFFFFFFFu, pred);
        if (pred) {
            int slot = sbase + __popc(bal & ltmask);
            if (slot < K_SEL) s_sel[w][slot] = d;
        }
        sbase += __popc(bal);
    }
    __syncwarp();

    // ---- bitonic sort 32 indices ascending -> ranks; u16 scratch write ----
    unsigned v = s_sel[w][lane];
    #pragma unroll
    for (int k = 2; k <= 32; k <<= 1) {
        #pragma unroll
        for (int j = k >> 1; j > 0; j >>= 1) {
            unsigned p = __shfl_xor_sync(0xFFFFFFFFu, v, j);
            bool up = ((lane & k) == 0);
            bool lower = ((lane & j) == 0);
            v = (lower == up) ? min(v, p) : max(v, p);
        }
    }
    g_sel[(size_t)row * K_SEL + lane] = (unsigned short)v;
}

// =============================================================================
// Kernel 2a: per-(b,w) partial sums in 512 independent blocks. Per-warp add
// order is EXACTLY the passing rounds' (n = w + 8i, i ascending, sequential
// adds) — bit-identical; only the parallelization across blocks changed.
// =============================================================================
__global__ void __launch_bounds__(32)
reduce_kernel(const float* __restrict__ wa) {
    const int b    = blockIdx.x;
    const int w    = blockIdx.y;    // 0..7
    const int lane = threadIdx.x;   // k
    const float* warow = wa + (size_t)b * D_SZ;
    const unsigned short* base = g_sel + (size_t)b * D_SZ * K_SEL;

    float acc = 0.0f;
    int i = 0;
    #pragma unroll 1
    for (; i + 8 <= 115; i += 8) {
        unsigned i0 = base[(w + 8 * (i + 0)) * K_SEL + lane];
        unsigned i1 = base[(w + 8 * (i + 1)) * K_SEL + lane];
        unsigned i2 = base[(w + 8 * (i + 2)) * K_SEL + lane];
        unsigned i3 = base[(w + 8 * (i + 3)) * K_SEL + lane];
        unsigned i4 = base[(w + 8 * (i + 4)) * K_SEL + lane];
        unsigned i5 = base[(w + 8 * (i + 5)) * K_SEL + lane];
        unsigned i6 = base[(w + 8 * (i + 6)) * K_SEL + lane];
        unsigned i7 = base[(w + 8 * (i + 7)) * K_SEL + lane];
        float v0 = __ldg(&warow[i0]), v1 = __ldg(&warow[i1]);
        float v2 = __ldg(&warow[i2]), v3 = __ldg(&warow[i3]);
        float v4 = __ldg(&warow[i4]), v5 = __ldg(&warow[i5]);
        float v6 = __ldg(&warow[i6]), v7 = __ldg(&warow[i7]);
        acc += v0; acc += v1; acc += v2; acc += v3;     // exact serial order
        acc += v4; acc += v5; acc += v6; acc += v7;
    }
    #pragma unroll 1
    for (; i < 115; ++i)
        acc += __ldg(&warow[base[(w + 8 * i) * K_SEL + lane]]);
    g_red[((size_t)b * 8 + w) * K_SEL + lane] = acc;
}

// =============================================================================
// Kernel 2b: combine the 8 partials in the EXACT same order, then bbox.
// =============================================================================
__global__ void __launch_bounds__(32)
bbox_kernel(float* __restrict__ out) {
    const int b = blockIdx.x;
    const int lane = threadIdx.x;   // k
    float s = 0.0f;
    #pragma unroll
    for (int j = 0; j < 8; j++) s += g_red[((size_t)b * 8 + j) * K_SEL + lane];
    s = s / (float)D_SZ;

    float r = floorf(__fdiv_rn(s, 40.0f));
    float c = __fadd_rn(s, -__fmul_rn(r, 40.0f));   // jnp.mod(s, 40)
    float x0 = __fmul_rn((c < 1.0f) ? c : (c - 1.0f), 32.0f);
    float y0 = __fmul_rn((r < 1.0f) ? r : (r - 1.0f), 32.0f);
    float x1 = __fmul_rn((c < 1.0f) ? (c + 2.0f) : (c + 1.0f), 32.0f);
    float y1 = __fmul_rn(r + 2.0f, 32.0f);
    reinterpret_cast<float4*>(out)[b * K_SEL + lane] = make_float4(x0, y0, x1, y1);
}

extern "C" void kernel_launch(void* const* d_in, const int* in_sizes, int n_in,
                              void* d_out, int out_size) {
    (void)in_sizes; (void)n_in; (void)out_size;
    const float* weight_attn = (const float*)d_in[2];   // (64, 23, 40)
    float* out = (float*)d_out;                          // (64, 32, 4)

    init_kernel<<<1, 64>>>();
    thresh_kernel<<<(B_SZ * D_SZ + 255) / 256, 256>>>(weight_attn);
    row_topk_kernel<<<NROWS / WARPS_PER_CTA, THREADS>>>(weight_attn);
    reduce_kernel<<<dim3(B_SZ, 8), 32>>>(weight_attn);
    bbox_kernel<<<B_SZ, 32>>>(out);
}

// round 16
// speedup vs baseline: 1.1184x; 1.1184x over previous
#include <cuda_runtime.h>
#include <cstdint>

// ---------------- problem constants ----------------
#define B_SZ    64
#define D_SZ    920          // 23*40
#define K_SEL   32
#define NROWS   (B_SZ * D_SZ)      // 58880 sample-rows (b, n)
#define WARPS_PER_CTA 8
#define THREADS (WARPS_PER_CTA * 32)
#define CAP     128
#define NBINS   128
#define T0F     0.90f        // prefilter threshold (exact-count fallback below)

// scratch (all __device__ globals; no allocations)
__device__ float               g_selval[NROWS * K_SEL];    // 7.5 MB selected VALUES
__device__ unsigned long long  g_act[B_SZ * D_SZ];         // per-b active list (tf<<32|d)
__device__ int                 g_actcnt[B_SZ];             // per-b active counts

// ---------------- threefry2x32, key=(0,1), partitionable fold ----------------
// Plain adds: ptxas balances IMAD/IADD3 across pipes itself.
__device__ __forceinline__ unsigned tf_bits(unsigned ctr) {
    unsigned x0 = 0u, x1 = ctr;
    const unsigned k0 = 0u, k1 = 1u, kx = 0x1BD11BDBu;
    x0 += k0; x1 += k1;
#define TFR(r) { x0 += x1; x1 = __funnelshift_l(x1, x1, (r)); x1 ^= x0; }
    TFR(13) TFR(15) TFR(26) TFR(6)
    x0 += k1; x1 += kx + 1u;
    TFR(17) TFR(29) TFR(16) TFR(24)
    x0 += kx; x1 += k0 + 2u;
    TFR(13) TFR(15) TFR(26) TFR(6)
    x0 += k0; x1 += k1 + 3u;
    TFR(17) TFR(29) TFR(16) TFR(24)
    x0 += k1; x1 += kx + 4u;
#undef TFR
    return x0 ^ x1;
}

// ---------------- XLA ErfInv32 (identical numerics to passing rounds) --------
__device__ __forceinline__ float erfinv_xla(float x) {
    float w = -log1pf(-__fmul_rn(x, x));
    float p;
    if (w < 5.0f) {
        w = w - 2.5f;
        p = 2.81022636e-08f;
        p = fmaf(p, w, 3.43273939e-07f);
        p = fmaf(p, w, -3.5233877e-06f);
        p = fmaf(p, w, -4.39150654e-06f);
        p = fmaf(p, w, 0.00021858087f);
        p = fmaf(p, w, -0.00125372503f);
        p = fmaf(p, w, -0.00417768164f);
        p = fmaf(p, w, 0.246640727f);
        p = fmaf(p, w, 1.50140941f);
    } else {
        w = sqrtf(w) - 3.0f;
        p = -0.000200214257f;
        p = fmaf(p, w, 0.000100950558f);
        p = fmaf(p, w, 0.00134934322f);
        p = fmaf(p, w, -0.00367342844f);
        p = fmaf(p, w, 0.00573950773f);
        p = fmaf(p, w, -0.0076224613f);
        p = fmaf(p, w, 0.00943887047f);
        p = fmaf(p, w, 1.00167406f);
        p = fmaf(p, w, 2.83297682f);
    }
    return __fmul_rn(p, x);
}

// exact perturbed value from the 23 uniform bits (must match all rounds' path)
__device__ __forceinline__ float pert_from_v23(unsigned v23, float wad) {
    float f = __uint_as_float(v23 | 0x3F800000u) - 1.0f;   // [0,1)
    float u = __fadd_rn(__fmul_rn(f, 2.0f), -0.99999994f);
    float nrm = __fmul_rn(1.41421356f, erfinv_xla(u));
    return __fadd_rn(wad, __fmul_rn(nrm, 0.1f));
}

__device__ __forceinline__ unsigned orderable(float v) {
    unsigned u = __float_as_uint(v);
    return (u & 0x80000000u) ? ~u : (u | 0x80000000u);
}
// monotone quantizer into 128 bins over the competitive range (~0.9..1.32)
__device__ __forceinline__ int qbin_of(float pert) {
    int q = (int)fmaf(pert, 300.0f, -260.0f);
    return min(NBINS - 1, max(0, q));
}

// =============================================================================
// Kernel 0 (R10-proven): one block per b. Per-d exact 23-step bisection for the
// minimal v23 with pert > T0; impossible d dropped. Survivors compacted via
// block scan (d-ascending, deterministic) into g_act[b] as (tfull<<32 | d),
// tfull = max(lo-64,0)<<9 (64-ULP conservative slack; superset filter).
// =============================================================================
__global__ void __launch_bounds__(1024)
thresh_compact_kernel(const float* __restrict__ wa) {
    const int b   = blockIdx.x;
    const int tid = threadIdx.x;
    const int lane = tid & 31, w = tid >> 5;
    __shared__ unsigned s_wcnt[32];
    __shared__ unsigned s_wbase[32];

    bool active = false;
    unsigned tf = 0u;
    if (tid < D_SZ) {
        float wad = wa[(size_t)b * D_SZ + tid];
        unsigned lo = 0u, hi = 0x800000u;
        #pragma unroll 1
        for (int it = 0; it < 24; ++it) {
            if (lo >= hi) break;
            unsigned mid = (lo + hi) >> 1;
            if (pert_from_v23(mid, wad) > T0F) hi = mid; else lo = mid + 1u;
        }
        if (lo < 0x800000u) {
            active = true;
            unsigned t = (lo >= 64u) ? (lo - 64u) : 0u;
            tf = t << 9;
        }
    }
    unsigned bal = __ballot_sync(0xFFFFFFFFu, active);
    if (lane == 0) s_wcnt[w] = __popc(bal);
    __syncthreads();
    if (w == 0) {
        unsigned v = s_wcnt[lane], acc = v;
        #pragma unroll
        for (int off = 1; off < 32; off <<= 1) {
            unsigned y = __shfl_up_sync(0xFFFFFFFFu, acc, off);
            if (lane >= off) acc += y;
        }
        s_wbase[lane] = acc - v;
        if (lane == 31) g_actcnt[b] = (int)acc;
    }
    __syncthreads();
    if (active) {
        int pos = (int)s_wbase[w] + __popc(bal & ((1u << lane) - 1u));
        g_act[(size_t)b * D_SZ + pos] =
            ((unsigned long long)tf << 32) | (unsigned)tid;
    }
}

// exact-pert generation pass (fallback only; full d scan, independent of g_act)
template<bool STORE>
__device__ __forceinline__ int gen_exact(const float* s_wa, unsigned gbase, float T,
                                         unsigned long long* cand, int lane) {
    const unsigned ltmask = (1u << lane) - 1u;
    int base = 0;
    for (int i = 0; i < 29; ++i) {
        int d = (i << 5) + lane;
        bool valid = (d < D_SZ);
        unsigned bits = valid ? tf_bits(gbase + (unsigned)d) : 0u;
        float pert = valid ? pert_from_v23(bits >> 9, s_wa[d]) : -1e30f;
        bool pred = valid && (pert > T);
        unsigned bal = __ballot_sync(0xFFFFFFFFu, pred);
        if (STORE && pred) {
            int slot = base + __popc(bal & ltmask);
            if (slot < CAP)
                cand[slot] = ((unsigned long long)bits << 32) | (unsigned)d;
        }
        base += __popc(bal);
    }
    return base;
}

// =============================================================================
// Kernel 1: warp-per-row; hot loop over the COMPACTED active list only
// (threefry + 32-bit compare). 4 independent chains per lane; candidate
// insertion via per-warp smem atomic (selection math is order-independent).
// Output: the 32 selected wa VALUES in ascending-index rank order.
// =============================================================================
__global__ void __launch_bounds__(THREADS)
row_topk_kernel(const float* __restrict__ wa) {
    __shared__ float              s_wa[D_SZ];
    __shared__ unsigned long long s_act[D_SZ];
    __shared__ unsigned long long s_cand[WARPS_PER_CTA][CAP];
    __shared__ unsigned           s_hist[WARPS_PER_CTA][NBINS];
    __shared__ unsigned char      s_qb[WARPS_PER_CTA][CAP];
    __shared__ unsigned           s_sel[WARPS_PER_CTA][K_SEL];
    __shared__ unsigned           s_chosen[WARPS_PER_CTA][CAP / 32];
    __shared__ int                s_cnt[WARPS_PER_CTA];

    const int tid  = threadIdx.x;
    const int w    = tid >> 5;
    const int lane = tid & 31;
    const int row  = blockIdx.x * WARPS_PER_CTA + w;
    const int b    = (blockIdx.x * WARPS_PER_CTA) / D_SZ;   // same b across CTA

    const int nact = g_actcnt[b];
    for (int d = tid; d < D_SZ; d += THREADS)
        s_wa[d] = wa[(size_t)b * D_SZ + d];
    for (int j = tid; j < nact; j += THREADS)
        s_act[j] = g_act[(size_t)b * D_SZ + j];
    if (lane == 0) s_cnt[w] = 0;
    __syncthreads();            // the only block barrier

    unsigned long long* cand = s_cand[w];
    const unsigned gbase  = (unsigned)row * (unsigned)D_SZ;
    const unsigned ltmask = (1u << lane) - 1u;

    // ---- integer-only generate over active list: 4 chains, no ballots ----
    const int nfull = nact & ~127;
    #pragma unroll 1
    for (int j0 = 0; j0 < nfull; j0 += 128) {
        int j = j0 + lane;
        unsigned long long e0 = s_act[j];
        unsigned long long e1 = s_act[j + 32];
        unsigned long long e2 = s_act[j + 64];
        unsigned long long e3 = s_act[j + 96];
        unsigned d0 = (unsigned)e0, d1 = (unsigned)e1,
                 d2 = (unsigned)e2, d3 = (unsigned)e3;
        unsigned bb0 = tf_bits(gbase + d0);
        unsigned bb1 = tf_bits(gbase + d1);
        unsigned bb2 = tf_bits(gbase + d2);
        unsigned bb3 = tf_bits(gbase + d3);
        if (bb0 >= (unsigned)(e0 >> 32)) {
            int s = atomicAdd(&s_cnt[w], 1);
            if (s < CAP) cand[s] = ((unsigned long long)bb0 << 32) | d0;
        }
        if (bb1 >= (unsigned)(e1 >> 32)) {
            int s = atomicAdd(&s_cnt[w], 1);
            if (s < CAP) cand[s] = ((unsigned long long)bb1 << 32) | d1;
        }
        if (bb2 >= (unsigned)(e2 >> 32)) {
            int s = atomicAdd(&s_cnt[w], 1);
            if (s < CAP) cand[s] = ((unsigned long long)bb2 << 32) | d2;
        }
        if (bb3 >= (unsigned)(e3 >> 32)) {
            int s = atomicAdd(&s_cnt[w], 1);
            if (s < CAP) cand[s] = ((unsigned long long)bb3 << 32) | d3;
        }
    }
    #pragma unroll 1
    for (int j0 = nfull; j0 < nact; j0 += 32) {     // remainder, 1 chain
        int j = j0 + lane;
        if (j < nact) {
            unsigned long long e = s_act[j];
            unsigned d = (unsigned)e;
            unsigned bb = tf_bits(gbase + d);
            if (bb >= (unsigned)(e >> 32)) {
                int s = atomicAdd(&s_cnt[w], 1);
                if (s < CAP) cand[s] = ((unsigned long long)bb << 32) | d;
            }
        }
    }
    __syncwarp();
    int m = s_cnt[w];

    // ---- exact pert/key conversion for candidates; exact above-T0 count ------
    auto convert = [&](int mm) -> int {
        int cnt = 0;
        for (int c = lane; c < mm; c += 32) {
            unsigned long long e = cand[c];
            unsigned bits = (unsigned)(e >> 32);
            unsigned d    = (unsigned)(e & 0xFFFFFFFFull);
            float pert = pert_from_v23(bits >> 9, s_wa[d]);
            cnt += (pert > T0F);
            cand[c] = ((unsigned long long)orderable(pert) << 32) | (unsigned)(~d);
            s_qb[w][c] = (unsigned char)qbin_of(pert);
        }
        __syncwarp();
        return __reduce_add_sync(0xFFFFFFFFu, cnt);
    };

    int mm = min(m, CAP);
    int mex = convert(mm);

    if (m > CAP || mex < K_SEL) {
        // exact fallback (never fires for this distribution): bisect a value
        // threshold with K_SEL <= count <= CAP using exact pert over ALL d
        float lo = -0.7f, hi = 1.6f, T = T0F;
        #pragma unroll 1
        for (int it = 0; it < 24; ++it) {
            T = 0.5f * (lo + hi);
            int c = gen_exact<false>(s_wa, gbase, T, cand, lane);
            if (c < K_SEL)      hi = T;
            else if (c > CAP)   lo = T;
            else break;
        }
        m  = gen_exact<true>(s_wa, gbase, T, cand, lane);
        mm = min(m, CAP);
        convert(mm);
    }

    // ---- fine histogram over mm candidates (128 bins) ----
    #pragma unroll
    for (int j = lane; j < NBINS; j += 32) s_hist[w][j] = 0u;
    __syncwarp();
    for (int c = lane; c < mm; c += 32)
        atomicAdd(&s_hist[w][s_qb[w][c]], 1u);
    __syncwarp();

    // ---- suffix scan: boundary bin Bq, count strictly above ----
    unsigned h[4], t = 0;
    #pragma unroll
    for (int j = 0; j < 4; ++j) { h[j] = s_hist[w][(lane << 2) + j]; t += h[j]; }
    unsigned x = t;
    #pragma unroll
    for (int off = 1; off < 32; off <<= 1) {
        unsigned y = __shfl_down_sync(0xFFFFFFFFu, x, off);
        if (lane + off < 32) x += y;
    }
    unsigned run = x - t;
    int Bq_l = -1; unsigned above_l = 0;
    #pragma unroll
    for (int j = 3; j >= 0; --j) {
        unsigned inc = run + h[j];
        if (run < K_SEL && inc >= K_SEL) { Bq_l = (lane << 2) + j; above_l = run; }
        run = inc;
    }
    unsigned fb = __ballot_sync(0xFFFFFFFFu, Bq_l >= 0);
    int src = __ffs(fb) - 1;
    const int      Bq    = __shfl_sync(0xFFFFFFFFu, Bq_l, src);
    const unsigned above = __shfl_sync(0xFFFFFFFFu, above_l, src);
    const unsigned need  = K_SEL - above;

    // ---- exact boundary tie-break: top `need` of bin Bq by (key desc, d asc) --
    #pragma unroll
    for (int j = lane; j < CAP / 32; j += 32) s_chosen[w][j] = 0u;
    __syncwarp();
    for (unsigned it = 0; it < need; ++it) {
        unsigned long long best = 0ull; int bpos = -1;
        for (int c = lane; c < mm; c += 32) {
            if (s_qb[w][c] == (unsigned char)Bq &&
                !((s_chosen[w][c >> 5] >> (c & 31)) & 1u)) {
                unsigned long long v = cand[c];
                if (v > best) { best = v; bpos = c; }
            }
        }
        #pragma unroll
        for (int off = 16; off; off >>= 1) {
            unsigned long long ob = __shfl_down_sync(0xFFFFFFFFu, best, off);
            int op = __shfl_down_sync(0xFFFFFFFFu, bpos, off);
            if (ob > best) { best = ob; bpos = op; }
        }
        bpos = __shfl_sync(0xFFFFFFFFu, bpos, 0);
        if (lane == 0 && bpos >= 0)                       // defensive: no wild write
            s_chosen[w][bpos >> 5] |= 1u << (bpos & 31);
        __syncwarp();
    }

    // ---- gather 32 selected indices (unordered) ----
    int sbase = 0;
    for (int c0 = 0; c0 < mm; c0 += 32) {
        int c = c0 + lane;
        bool pred = false; unsigned d = 0;
        if (c < mm) {
            bool win = ((int)s_qb[w][c] > Bq) ||
                       (((s_chosen[w][c >> 5] >> (c & 31)) & 1u) != 0u);
            if (win) { pred = true; d = ~(unsigned)(cand[c] & 0xFFFFFFFFull); }
        }
        unsigned bal = __ballot_sync(0xFFFFFFFFu, pred);
        if (pred) {
            int slot = sbase + __popc(bal & ltmask);
            if (slot < K_SEL) s_sel[w][slot] = d;
        }
        sbase += __popc(bal);
    }
    __syncwarp();

    // ---- bitonic sort 32 indices ascending -> ranks; store VALUES ----
    unsigned v = s_sel[w][lane];
    #pragma unroll
    for (int k = 2; k <= 32; k <<= 1) {
        #pragma unroll
        for (int j = k >> 1; j > 0; j >>= 1) {
            unsigned p = __shfl_xor_sync(0xFFFFFFFFu, v, j);
            bool up = ((lane & k) == 0);
            bool lower = ((lane & j) == 0);
            v = (lower == up) ? min(v, p) : max(v, p);
        }
    }
    g_selval[(size_t)row * K_SEL + lane] = s_wa[v];   // value, not index
}

// =============================================================================
// Kernel 2: fused streaming reduce + bbox, one block per b. Warp w sums
// val[(w+8i)*32+lane] for i = 0..114 in EXACTLY the historical sequential
// order (same floats, same order -> bit-identical), but with single-level
// perfectly-coalesced loads (no index gather, no smem stage). Warp 0 then
// combines red[0..7] in the exact same order and emits the bbox.
// =============================================================================
__global__ void __launch_bounds__(256)
finalize_kernel(float* __restrict__ out) {
    const int b    = blockIdx.x;
    const int tid  = threadIdx.x;
    const int w    = tid >> 5;      // 8 sample groups
    const int lane = tid & 31;      // k
    __shared__ float red[8][32];

    const float* base = g_selval + (size_t)b * D_SZ * K_SEL;
    float acc = 0.0f;
    int i = 0;
    #pragma unroll 1
    for (; i + 8 <= 115; i += 8) {          // n = w + 8*(i+t), t = 0..7
        float v0 = base[(w + 8 * (i + 0)) * K_SEL + lane];
        float v1 = base[(w + 8 * (i + 1)) * K_SEL + lane];
        float v2 = base[(w + 8 * (i + 2)) * K_SEL + lane];
        float v3 = base[(w + 8 * (i + 3)) * K_SEL + lane];
        float v4 = base[(w + 8 * (i + 4)) * K_SEL + lane];
        float v5 = base[(w + 8 * (i + 5)) * K_SEL + lane];
        float v6 = base[(w + 8 * (i + 6)) * K_SEL + lane];
        float v7 = base[(w + 8 * (i + 7)) * K_SEL + lane];
        acc += v0; acc += v1; acc += v2; acc += v3;     // exact serial order
        acc += v4; acc += v5; acc += v6; acc += v7;
    }
    #pragma unroll 1
    for (; i < 115; ++i)
        acc += base[(w + 8 * i) * K_SEL + lane];
    red[w][lane] = acc;
    __syncthreads();

    if (w == 0) {
        float s = 0.0f;
        #pragma unroll
        for (int j = 0; j < 8; j++) s += red[j][lane];
        s = s / (float)D_SZ;

        float r = floorf(__fdiv_rn(s, 40.0f));
        float c = __fadd_rn(s, -__fmul_rn(r, 40.0f));   // jnp.mod(s, 40)
        float x0 = __fmul_rn((c < 1.0f) ? c : (c - 1.0f), 32.0f);
        float y0 = __fmul_rn((r < 1.0f) ? r : (r - 1.0f), 32.0f);
        float x1 = __fmul_rn((c < 1.0f) ? (c + 2.0f) : (c + 1.0f), 32.0f);
        float y1 = __fmul_rn(r + 2.0f, 32.0f);
        reinterpret_cast<float4*>(out)[b * K_SEL + lane] = make_float4(x0, y0, x1, y1);
    }
}

extern "C" void kernel_launch(void* const* d_in, const int* in_sizes, int n_in,
                              void* d_out, int out_size) {
    (void)in_sizes; (void)n_in; (void)out_size;
    const float* weight_attn = (const float*)d_in[2];   // (64, 23, 40)
    float* out = (float*)d_out;                          // (64, 32, 4)

    thresh_compact_kernel<<<B_SZ, 1024>>>(weight_attn);
    row_topk_kernel<<<NROWS / WARPS_PER_CTA, THREADS>>>(weight_attn);
    finalize_kernel<<<B_SZ, 256>>>(out);
}